// round 16
// baseline (speedup 1.0000x reference)
#include <cuda_runtime.h>

#define NN   50000
#define EE   800000
#define IND  128
#define OUTD 64
#define EDD  32

typedef unsigned long long ull;

// ---------------- scratch (static device arrays; no allocation) ----------------
__device__ __align__(16) float g_z[NN * OUTD];     // z = x@W_fc + b_fc
__device__ float g_asrc[NN];                       // z . Wa[0:64]
__device__ float g_adst[NN];                       // z . Wa[64:128]
__device__ int   g_deg[NN];                        // in-degree per dst
__device__ int   g_start[NN];                      // CSR start offsets
__device__ int   g_cursor[NN];                     // fill cursor per dst
__device__ __align__(16) float4 g_pack[EE];        // {p, row, e, -} per CSR slot

// ---------------- helpers ----------------
__device__ __forceinline__ ull bcast2(float x) {
    ull r; asm("mov.b64 %0, {%1, %1};" : "=l"(r) : "f"(x)); return r;
}
__device__ __forceinline__ ull pack2f(float2 v) {
    ull r; asm("mov.b64 %0, {%1, %2};" : "=l"(r) : "f"(v.x), "f"(v.y)); return r;
}
__device__ __forceinline__ float2 unpack2(ull v) {
    float2 r; asm("mov.b64 {%0, %1}, %2;" : "=f"(r.x), "=f"(r.y) : "l"(v)); return r;
}
// packed f32x2 fma: acc = a*b + acc (2 fp32 lanes per instruction)
__device__ __forceinline__ void fma2(ull& acc, ull a, ull b) {
    asm("fma.rn.f32x2 %0, %1, %2, %0;" : "+l"(acc) : "l"(a), "l"(b));
}
__device__ __forceinline__ float wredsum(float v) {
#pragma unroll
    for (int o = 16; o > 0; o >>= 1) v += __shfl_xor_sync(0xffffffffu, v, o);
    return v;
}

// ---------------- K1: node transforms (8 nodes / warp / iter) ----------------
// z = x@W_fc + b_fc ; out = x@W_self + b_self ; a_src/a_dst node scalars.
// Also zeroes g_deg for this launch (ordered before k2a by the launch boundary).
__global__ void __launch_bounds__(256, 2)
k1_node(const float* __restrict__ x,
        const float* __restrict__ Wfc,   const float* __restrict__ bfc,
        const float* __restrict__ Wself, const float* __restrict__ bself,
        const float* __restrict__ Wattn,
        float* __restrict__ out)
{
    extern __shared__ float sm[];
    float* sWfc = sm;                     // 128*64
    float* sWs  = sm + IND * OUTD;        // 128*64
    float* sx   = sm + 2 * IND * OUTD;    // 8 warps * 8 nodes * 128
    const int tid = threadIdx.x;

    {   // zero degree counters
        int gt = blockIdx.x * blockDim.x + tid;
        int gs = gridDim.x * blockDim.x;
        for (int i = gt; i < NN; i += gs) g_deg[i] = 0;
    }
    for (int i = tid; i < (IND * OUTD) / 4; i += blockDim.x) {
        ((float4*)sWfc)[i] = ((const float4*)Wfc)[i];
        ((float4*)sWs)[i]  = ((const float4*)Wself)[i];
    }
    __syncthreads();

    const int warp = tid >> 5, lane = tid & 31;
    const int gw = blockIdx.x * 8 + warp, nw = gridDim.x * 8;
    float* sxw = sx + warp * (8 * IND);

    const ull bfp = pack2f(((const float2*)bfc)[lane]);
    const ull bsp = pack2f(((const float2*)bself)[lane]);
    const float wa_s0 = Wattn[2 * lane],        wa_s1 = Wattn[2 * lane + 1];
    const float wa_d0 = Wattn[OUTD + 2 * lane], wa_d1 = Wattn[OUTD + 2 * lane + 1];

    for (int n0 = gw * 8; n0 < NN; n0 += nw * 8) {      // 50000 % 8 == 0
#pragma unroll
        for (int k = 0; k < 8; k++)
            ((float4*)(sxw + k * IND))[lane] =
                ((const float4*)(x + (size_t)(n0 + k) * IND))[lane];
        __syncwarp();

        ull aF[8], aS[8];
#pragma unroll
        for (int k = 0; k < 8; k++) { aF[k] = bfp; aS[k] = bsp; }

#pragma unroll 1
        for (int d4 = 0; d4 < IND / 4; d4++) {
            float4 xq[8];
#pragma unroll
            for (int k = 0; k < 8; k++)
                xq[k] = ((const float4*)(sxw + k * IND))[d4];   // broadcast LDS.128
#pragma unroll
            for (int dd = 0; dd < 4; dd++) {
                const int d = d4 * 4 + dd;
                ull wf = ((const ull*)(sWfc + d * OUTD))[lane];
                ull ws = ((const ull*)(sWs  + d * OUTD))[lane];
#pragma unroll
                for (int k = 0; k < 8; k++) {
                    float xv = (dd == 0) ? xq[k].x : (dd == 1) ? xq[k].y
                             : (dd == 2) ? xq[k].z : xq[k].w;
                    ull xb = bcast2(xv);
                    fma2(aF[k], xb, wf);
                    fma2(aS[k], xb, ws);
                }
            }
        }
#pragma unroll
        for (int k = 0; k < 8; k++) {
            float2 z = unpack2(aF[k]);
            ((float2*)(g_z + (size_t)(n0 + k) * OUTD))[lane] = z;
            ((float2*)(out + (size_t)(n0 + k) * OUTD))[lane] = unpack2(aS[k]);
            float ps = wredsum(z.x * wa_s0 + z.y * wa_s1);
            float pd = wredsum(z.x * wa_d0 + z.y * wa_d1);
            if (lane == 0) { g_asrc[n0 + k] = ps; g_adst[n0 + k] = pd; }
        }
        __syncwarp();
    }
}

// ---------------- K2a: in-degree count ----------------
__global__ void k2a_deg(const int* __restrict__ eidx)
{
    int e = blockIdx.x * blockDim.x + threadIdx.x;   // grid exact
    atomicAdd(&g_deg[__ldg(eidx + EE + e)], 1);
}

// ---------------- K2b: exclusive scan of degrees (single block) ----------------
__global__ void k2b_scan()
{
    __shared__ int swarp[32];
    const int tid = threadIdx.x, lane = tid & 31, w = tid >> 5;
    int carry = 0;
    for (int base = 0; base < NN; base += 1024) {
        int i = base + tid;
        int v = (i < NN) ? g_deg[i] : 0;
        int sv = v;
#pragma unroll
        for (int o = 1; o < 32; o <<= 1) {
            int t = __shfl_up_sync(0xffffffffu, sv, o);
            if (lane >= o) sv += t;
        }
        if (lane == 31) swarp[w] = sv;
        __syncthreads();
        if (w == 0) {
            int ws = swarp[lane];
#pragma unroll
            for (int o = 1; o < 32; o <<= 1) {
                int t = __shfl_up_sync(0xffffffffu, ws, o);
                if (lane >= o) ws += t;
            }
            swarp[lane] = ws;
        }
        __syncthreads();
        int excl = carry + (w > 0 ? swarp[w - 1] : 0) + sv - v;
        if (i < NN) { g_start[i] = excl; g_cursor[i] = excl; }
        int tot = swarp[31];
        __syncthreads();          // protect swarp before next iteration
        carry += tot;
    }
}

// ---------------- K2c: edge logits -> packed CSR records ----------------
// 4 lanes/edge (8 edges/warp): 32-dot of edge_attr with Wa[128:160], then
// p = exp(leaky(a_src+a_dst+dot+b)); record {p,row,e} at col's next CSR slot.
// ONE atomic per edge; tail runs on 8 concurrent lanes per warp.
__global__ void k2c_edge(const float* __restrict__ ea, const int* __restrict__ eidx,
                         const float* __restrict__ Wattn, const float* __restrict__ battn)
{
    int gt = blockIdx.x * blockDim.x + threadIdx.x;
    int e  = gt >> 2, sl = gt & 3;                    // grid exact: e < EE

    const float4* eap = (const float4*)(ea + (size_t)e * EDD);
    float4 ev0 = eap[sl];
    float4 ev1 = eap[sl + 4];
    float4 w0  = __ldg((const float4*)(Wattn + 2 * OUTD) + sl);
    float4 w1  = __ldg((const float4*)(Wattn + 2 * OUTD) + sl + 4);
    float s = ev0.x * w0.x + ev0.y * w0.y + ev0.z * w0.z + ev0.w * w0.w
            + ev1.x * w1.x + ev1.y * w1.y + ev1.z * w1.z + ev1.w * w1.w;
    s += __shfl_xor_sync(0xffffffffu, s, 2);
    s += __shfl_xor_sync(0xffffffffu, s, 1);

    if (sl == 0) {
        int row = __ldg(eidx + e);
        int col = __ldg(eidx + EE + e);
        float logit = g_asrc[row] + g_adst[col] + s + battn[0];
        float lr = logit > 0.f ? logit : 0.2f * logit;
        float p  = __expf(lr);   // logits bounded ~|6|: max-shift elided, alpha unchanged
        int pos = atomicAdd(&g_cursor[col], 1);
        g_pack[pos] = make_float4(p, __int_as_float(row), __int_as_float(e), 0.f);
    }
}

// ---------------- K3: gather + full epilogue (one warp per dst node) ----------------
// accZ = sum p*z[row]; accG = sum p*ea[e]; den = sum p  -- register accumulation,
// zero atomics, 8 independent load chains in flight.
// Then out[n] += (accZ + accG@W_edge)/den + (deg>0 ? b_edge : 0).
__global__ void __launch_bounds__(256)
k3_gather(const float* __restrict__ ea, const float* __restrict__ We,
          const float* __restrict__ be, float* __restrict__ out)
{
    __shared__ __align__(16) float sWe[EDD * OUTD];
    __shared__ float sbe[OUTD];
    const int tid = threadIdx.x;
    for (int i = tid; i < (EDD * OUTD) / 4; i += blockDim.x)
        ((float4*)sWe)[i] = ((const float4*)We)[i];
    if (tid < OUTD) sbe[tid] = be[tid];
    __syncthreads();

    const int warp = tid >> 5, lane = tid & 31;
    const int n = blockIdx.x * 8 + warp;              // grid exact: n < NN
    const int start = g_start[n], deg = g_deg[n];
    const int jend = start + deg;

    ull accZ = 0;
    float accG = 0.f, den = 0.f;
    const float4* __restrict__ pk = g_pack;

#define GSTEP(P)                                                              \
    {   float p = (P).x;                                                      \
        int row = __float_as_int((P).y);                                      \
        int e   = __float_as_int((P).z);                                      \
        float2 z2 = ((const float2*)(g_z + (size_t)row * OUTD))[lane];        \
        float eav = __ldg(ea + (size_t)e * EDD + lane);                       \
        fma2(accZ, bcast2(p), pack2f(z2));                                    \
        accG = fmaf(p, eav, accG);                                            \
        den += p; }

    int j = start;
    for (; j + 8 <= jend; j += 8) {                   // 8 independent chains (MLP=8)
        float4 P[8];
#pragma unroll
        for (int q = 0; q < 8; q++) P[q] = __ldg(pk + j + q);
#pragma unroll
        for (int q = 0; q < 8; q++) GSTEP(P[q])
    }
    if (j + 4 <= jend) {
        float4 P0 = __ldg(pk + j);
        float4 P1 = __ldg(pk + j + 1);
        float4 P2 = __ldg(pk + j + 2);
        float4 P3 = __ldg(pk + j + 3);
        GSTEP(P0) GSTEP(P1) GSTEP(P2) GSTEP(P3)
        j += 4;
    }
    for (; j < jend; j++) { float4 P = __ldg(pk + j); GSTEP(P) }
#undef GSTEP

    float inv = 1.f / fmaxf(den, 1e-16f);
    float g = accG * inv;                             // lane = edge-feature channel
    float acc0 = 0.f, acc1 = 0.f;
#pragma unroll
    for (int d = 0; d < EDD; d++) {
        float gd = __shfl_sync(0xffffffffu, g, d);
        float2 wv = ((const float2*)(sWe + d * OUTD))[lane];
        acc0 = fmaf(gd, wv.x, acc0);
        acc1 = fmaf(gd, wv.y, acc1);
    }
    float2 z = unpack2(accZ);
    float add0 = z.x * inv + acc0;
    float add1 = z.y * inv + acc1;
    if (deg > 0) { add0 += sbe[2 * lane]; add1 += sbe[2 * lane + 1]; }
    float2* op = (float2*)(out + (size_t)n * OUTD) + lane;
    float2 o = *op;
    o.x += add0; o.y += add1;
    *op = o;
}

// ---------------- launch ----------------
extern "C" void kernel_launch(void* const* d_in, const int* in_sizes, int n_in,
                              void* d_out, int out_size)
{
    const float* x     = (const float*)d_in[0];
    const float* ea    = (const float*)d_in[1];
    const int*   eidx  = (const int*)  d_in[2];
    const float* Wfc   = (const float*)d_in[3];
    const float* bfc   = (const float*)d_in[4];
    const float* Wattn = (const float*)d_in[5];
    const float* battn = (const float*)d_in[6];
    const float* Wedge = (const float*)d_in[7];
    const float* bedge = (const float*)d_in[8];
    const float* Wself = (const float*)d_in[9];
    const float* bself = (const float*)d_in[10];
    float* out = (float*)d_out;

    // weights 64KB + x staging 8 warps * 8 nodes * 128 floats = 32KB -> 96KB/block
    const size_t smem1 = (2 * IND * OUTD + 8 * 8 * IND) * sizeof(float);  // 98304 B
    cudaFuncSetAttribute(k1_node, cudaFuncAttributeMaxDynamicSharedMemorySize, (int)smem1);

    k1_node<<<296, 256, smem1>>>(x, Wfc, bfc, Wself, bself, Wattn, out);
    k2a_deg<<<EE / 256, 256>>>(eidx);                    // 3125 blocks, exact
    k2b_scan<<<1, 1024>>>();
    k2c_edge<<<(EE * 4) / 256, 256>>>(ea, eidx, Wattn, battn);   // 12500 blocks, exact
    k3_gather<<<(NN * 32) / 256, 256>>>(ea, Wedge, bedge, out);  // 6250 blocks, exact
}

// round 17
// speedup vs baseline: 1.0885x; 1.0885x over previous
#include <cuda_runtime.h>

#define NN   50000
#define EE   800000
#define IND  128
#define OUTD 64
#define EDD  32

typedef unsigned long long ull;

// ---------------- scratch (static device arrays; no allocation) ----------------
// g_deg is zeroed at the END of k3 each run (and is statically zero at process
// start), so k1 can count degrees without a separate zeroing pass.
__device__ __align__(16) float g_z[NN * OUTD];     // z = x@W_fc + b_fc
__device__ float g_asrc[NN];                       // z . Wa[0:64]
__device__ float g_adst[NN];                       // z . Wa[64:128]
__device__ int   g_deg[NN];                        // in-degree per dst
__device__ int   g_start[NN];                      // CSR start offsets
__device__ int   g_cursor[NN];                     // fill cursor per dst
__device__ __align__(16) float4 g_pack[EE];        // {p, row, e, -} per CSR slot

// ---------------- helpers ----------------
__device__ __forceinline__ ull bcast2(float x) {
    ull r; asm("mov.b64 %0, {%1, %1};" : "=l"(r) : "f"(x)); return r;
}
__device__ __forceinline__ ull pack2f(float2 v) {
    ull r; asm("mov.b64 %0, {%1, %2};" : "=l"(r) : "f"(v.x), "f"(v.y)); return r;
}
__device__ __forceinline__ float2 unpack2(ull v) {
    float2 r; asm("mov.b64 {%0, %1}, %2;" : "=f"(r.x), "=f"(r.y) : "l"(v)); return r;
}
// packed f32x2 fma: acc = a*b + acc (2 fp32 lanes per instruction)
__device__ __forceinline__ void fma2(ull& acc, ull a, ull b) {
    asm("fma.rn.f32x2 %0, %1, %2, %0;" : "+l"(acc) : "l"(a), "l"(b));
}
__device__ __forceinline__ float wredsum(float v) {
#pragma unroll
    for (int o = 16; o > 0; o >>= 1) v += __shfl_xor_sync(0xffffffffu, v, o);
    return v;
}

// ---------------- K1: node transforms (8 nodes / warp / iter) + degree count ----
// z = x@W_fc + b_fc ; out = x@W_self + b_self ; a_src/a_dst node scalars.
// Degree counting fused here (g_deg pre-zeroed by the previous k3 / static init);
// the REDG traffic hides under the FMA-saturated mainloop.
__global__ void __launch_bounds__(256, 2)
k1_node(const float* __restrict__ x,
        const float* __restrict__ Wfc,   const float* __restrict__ bfc,
        const float* __restrict__ Wself, const float* __restrict__ bself,
        const float* __restrict__ Wattn, const int* __restrict__ eidx,
        float* __restrict__ out)
{
    extern __shared__ float sm[];
    float* sWfc = sm;                     // 128*64
    float* sWs  = sm + IND * OUTD;        // 128*64
    float* sx   = sm + 2 * IND * OUTD;    // 8 warps * 8 nodes * 128
    const int tid = threadIdx.x;

    {   // fused in-degree count (one atomic per edge, hidden under compute)
        int gt = blockIdx.x * blockDim.x + tid;
        int gs = gridDim.x * blockDim.x;
        for (int e = gt; e < EE; e += gs)
            atomicAdd(&g_deg[__ldg(eidx + EE + e)], 1);
    }
    for (int i = tid; i < (IND * OUTD) / 4; i += blockDim.x) {
        ((float4*)sWfc)[i] = ((const float4*)Wfc)[i];
        ((float4*)sWs)[i]  = ((const float4*)Wself)[i];
    }
    __syncthreads();

    const int warp = tid >> 5, lane = tid & 31;
    const int gw = blockIdx.x * 8 + warp, nw = gridDim.x * 8;
    float* sxw = sx + warp * (8 * IND);

    const ull bfp = pack2f(((const float2*)bfc)[lane]);
    const ull bsp = pack2f(((const float2*)bself)[lane]);
    const float wa_s0 = Wattn[2 * lane],        wa_s1 = Wattn[2 * lane + 1];
    const float wa_d0 = Wattn[OUTD + 2 * lane], wa_d1 = Wattn[OUTD + 2 * lane + 1];

    for (int n0 = gw * 8; n0 < NN; n0 += nw * 8) {      // 50000 % 8 == 0
#pragma unroll
        for (int k = 0; k < 8; k++)
            ((float4*)(sxw + k * IND))[lane] =
                ((const float4*)(x + (size_t)(n0 + k) * IND))[lane];
        __syncwarp();

        ull aF[8], aS[8];
#pragma unroll
        for (int k = 0; k < 8; k++) { aF[k] = bfp; aS[k] = bsp; }

#pragma unroll 2
        for (int d2 = 0; d2 < IND / 2; d2++) {
            float2 xq[8];
#pragma unroll
            for (int k = 0; k < 8; k++)
                xq[k] = ((const float2*)(sxw + k * IND))[d2];   // broadcast LDS.64
#pragma unroll
            for (int dd = 0; dd < 2; dd++) {
                const int d = d2 * 2 + dd;
                ull wf = ((const ull*)(sWfc + d * OUTD))[lane];
                ull ws = ((const ull*)(sWs  + d * OUTD))[lane];
#pragma unroll
                for (int k = 0; k < 8; k++) {
                    ull xv = bcast2(dd == 0 ? xq[k].x : xq[k].y);
                    fma2(aF[k], xv, wf);
                    fma2(aS[k], xv, ws);
                }
            }
        }
#pragma unroll
        for (int k = 0; k < 8; k++) {
            float2 z = unpack2(aF[k]);
            ((float2*)(g_z + (size_t)(n0 + k) * OUTD))[lane] = z;
            ((float2*)(out + (size_t)(n0 + k) * OUTD))[lane] = unpack2(aS[k]);
            float ps = wredsum(z.x * wa_s0 + z.y * wa_s1);
            float pd = wredsum(z.x * wa_d0 + z.y * wa_d1);
            if (lane == 0) { g_asrc[n0 + k] = ps; g_adst[n0 + k] = pd; }
        }
        __syncwarp();
    }
}

// ---------------- K2b: exclusive scan of degrees (single block) ----------------
__global__ void k2b_scan()
{
    __shared__ int swarp[32];
    const int tid = threadIdx.x, lane = tid & 31, w = tid >> 5;
    int carry = 0;
    for (int base = 0; base < NN; base += 1024) {
        int i = base + tid;
        int v = (i < NN) ? g_deg[i] : 0;
        int sv = v;
#pragma unroll
        for (int o = 1; o < 32; o <<= 1) {
            int t = __shfl_up_sync(0xffffffffu, sv, o);
            if (lane >= o) sv += t;
        }
        if (lane == 31) swarp[w] = sv;
        __syncthreads();
        if (w == 0) {
            int ws = swarp[lane];
#pragma unroll
            for (int o = 1; o < 32; o <<= 1) {
                int t = __shfl_up_sync(0xffffffffu, ws, o);
                if (lane >= o) ws += t;
            }
            swarp[lane] = ws;
        }
        __syncthreads();
        int excl = carry + (w > 0 ? swarp[w - 1] : 0) + sv - v;
        if (i < NN) { g_start[i] = excl; g_cursor[i] = excl; }
        int tot = swarp[31];
        __syncthreads();          // protect swarp before next iteration
        carry += tot;
    }
}

// ---------------- K2c: edge logits -> packed CSR records ----------------
// 4 lanes/edge (8 edges/warp): 32-dot of edge_attr with Wa[128:160], then
// p = exp(leaky(a_src+a_dst+dot+b)); record {p,row,e} at col's next CSR slot.
// ONE atomic per edge; tail runs on 8 concurrent lanes per warp.
__global__ void k2c_edge(const float* __restrict__ ea, const int* __restrict__ eidx,
                         const float* __restrict__ Wattn, const float* __restrict__ battn)
{
    int gt = blockIdx.x * blockDim.x + threadIdx.x;
    int e  = gt >> 2, sl = gt & 3;                    // grid exact: e < EE

    const float4* eap = (const float4*)(ea + (size_t)e * EDD);
    float4 ev0 = eap[sl];
    float4 ev1 = eap[sl + 4];
    float4 w0  = __ldg((const float4*)(Wattn + 2 * OUTD) + sl);
    float4 w1  = __ldg((const float4*)(Wattn + 2 * OUTD) + sl + 4);
    float s = ev0.x * w0.x + ev0.y * w0.y + ev0.z * w0.z + ev0.w * w0.w
            + ev1.x * w1.x + ev1.y * w1.y + ev1.z * w1.z + ev1.w * w1.w;
    s += __shfl_xor_sync(0xffffffffu, s, 2);
    s += __shfl_xor_sync(0xffffffffu, s, 1);

    if (sl == 0) {
        int row = __ldg(eidx + e);
        int col = __ldg(eidx + EE + e);
        float logit = g_asrc[row] + g_adst[col] + s + battn[0];
        float lr = logit > 0.f ? logit : 0.2f * logit;
        float p  = __expf(lr);   // logits bounded ~|6|: max-shift elided, alpha unchanged
        int pos = atomicAdd(&g_cursor[col], 1);
        g_pack[pos] = make_float4(p, __int_as_float(row), __int_as_float(e), 0.f);
    }
}

// ---------------- K3: gather + full epilogue (one warp per dst node) ----------------
// accZ = sum p*z[row]; accG = sum p*ea[e]; den = sum p  -- register accumulation,
// zero atomics. Then out[n] += (accZ + accG@W_edge)/den + (deg>0 ? b_edge : 0).
// Finally RESETS g_deg[n]=0 so the next run's k1 can count without a zero pass.
__global__ void __launch_bounds__(256)
k3_gather(const float* __restrict__ ea, const float* __restrict__ We,
          const float* __restrict__ be, float* __restrict__ out)
{
    __shared__ __align__(16) float sWe[EDD * OUTD];
    __shared__ float sbe[OUTD];
    const int tid = threadIdx.x;
    for (int i = tid; i < (EDD * OUTD) / 4; i += blockDim.x)
        ((float4*)sWe)[i] = ((const float4*)We)[i];
    if (tid < OUTD) sbe[tid] = be[tid];
    __syncthreads();

    const int warp = tid >> 5, lane = tid & 31;
    const int n = blockIdx.x * 8 + warp;              // grid exact: n < NN
    const int start = g_start[n], deg = g_deg[n];
    const int jend = start + deg;

    ull accZ = 0;
    float accG = 0.f, den = 0.f;
    const float4* __restrict__ pk = g_pack;

#define GSTEP(P)                                                              \
    {   float p = (P).x;                                                      \
        int row = __float_as_int((P).y);                                      \
        int e   = __float_as_int((P).z);                                      \
        float2 z2 = ((const float2*)(g_z + (size_t)row * OUTD))[lane];        \
        float eav = __ldg(ea + (size_t)e * EDD + lane);                       \
        fma2(accZ, bcast2(p), pack2f(z2));                                    \
        accG = fmaf(p, eav, accG);                                            \
        den += p; }

    int j = start;
    for (; j + 4 <= jend; j += 4) {                   // 4 independent chains (MLP=4)
        float4 P0 = __ldg(pk + j);
        float4 P1 = __ldg(pk + j + 1);
        float4 P2 = __ldg(pk + j + 2);
        float4 P3 = __ldg(pk + j + 3);
        GSTEP(P0) GSTEP(P1) GSTEP(P2) GSTEP(P3)
    }
    for (; j < jend; j++) { float4 P = __ldg(pk + j); GSTEP(P) }
#undef GSTEP

    if (lane == 0) g_deg[n] = 0;                      // re-arm for next run

    float inv = 1.f / fmaxf(den, 1e-16f);
    float g = accG * inv;                             // lane = edge-feature channel
    float acc0 = 0.f, acc1 = 0.f;
#pragma unroll
    for (int d = 0; d < EDD; d++) {
        float gd = __shfl_sync(0xffffffffu, g, d);
        float2 wv = ((const float2*)(sWe + d * OUTD))[lane];
        acc0 = fmaf(gd, wv.x, acc0);
        acc1 = fmaf(gd, wv.y, acc1);
    }
    float2 z = unpack2(accZ);
    float add0 = z.x * inv + acc0;
    float add1 = z.y * inv + acc1;
    if (deg > 0) { add0 += sbe[2 * lane]; add1 += sbe[2 * lane + 1]; }
    float2* op = (float2*)(out + (size_t)n * OUTD) + lane;
    float2 o = *op;
    o.x += add0; o.y += add1;
    *op = o;
}

// ---------------- launch ----------------
extern "C" void kernel_launch(void* const* d_in, const int* in_sizes, int n_in,
                              void* d_out, int out_size)
{
    const float* x     = (const float*)d_in[0];
    const float* ea    = (const float*)d_in[1];
    const int*   eidx  = (const int*)  d_in[2];
    const float* Wfc   = (const float*)d_in[3];
    const float* bfc   = (const float*)d_in[4];
    const float* Wattn = (const float*)d_in[5];
    const float* battn = (const float*)d_in[6];
    const float* Wedge = (const float*)d_in[7];
    const float* bedge = (const float*)d_in[8];
    const float* Wself = (const float*)d_in[9];
    const float* bself = (const float*)d_in[10];
    float* out = (float*)d_out;

    // weights 64KB + x staging 8 warps * 8 nodes * 128 floats = 32KB -> 96KB/block
    const size_t smem1 = (2 * IND * OUTD + 8 * 8 * IND) * sizeof(float);  // 98304 B
    cudaFuncSetAttribute(k1_node, cudaFuncAttributeMaxDynamicSharedMemorySize, (int)smem1);

    k1_node<<<296, 256, smem1>>>(x, Wfc, bfc, Wself, bself, Wattn, eidx, out);
    k2b_scan<<<1, 1024>>>();
    k2c_edge<<<(EE * 4) / 256, 256>>>(ea, eidx, Wattn, battn);   // 12500 blocks, exact
    k3_gather<<<(NN * 32) / 256, 256>>>(ea, Wedge, bedge, out);  // 6250 blocks, exact
}